// round 12
// baseline (speedup 1.0000x reference)
#include <cuda_runtime.h>
#include <math.h>

#define NN 512
#define DF 256
typedef unsigned long long u64;

// ---------------- f32x2 helpers ----------------
__device__ __forceinline__ u64 pk2(float x) {
    u64 r; unsigned xi = __float_as_uint(x);
    asm("mov.b64 %0, {%1, %1};" : "=l"(r) : "r"(xi));
    return r;
}
__device__ __forceinline__ u64 pk2b(float lo, float hi) {
    u64 r; unsigned a = __float_as_uint(lo), b = __float_as_uint(hi);
    asm("mov.b64 %0, {%1, %2};" : "=l"(r) : "r"(a), "r"(b));
    return r;
}
__device__ __forceinline__ float2 unpk(u64 v) {
    unsigned a, b;
    asm("mov.b64 {%0, %1}, %2;" : "=r"(a), "=r"(b) : "l"(v));
    return make_float2(__uint_as_float(a), __uint_as_float(b));
}
__device__ __forceinline__ u64 ffma2(u64 a, u64 b, u64 c) {
    u64 r;
    asm("fma.rn.f32x2 %0, %1, %2, %3;" : "=l"(r) : "l"(a), "l"(b), "l"(c));
    return r;
}
__device__ __forceinline__ u64 fadd2(u64 a, u64 b) {
    u64 r;
    asm("add.rn.f32x2 %0, %1, %2;" : "=l"(r) : "l"(a), "l"(b));
    return r;
}
#define ABS2 0x7fffffff7fffffffULL

// ---------------- scratch ----------------
__device__ float g_Wh1s[2][NN*DF];
__device__ float g_Ars[2][NN*DF];
__device__ float g_Brs[2][NN*DF];
__device__ float g_hidTs[4][NN*DF];
__device__ float g_hidPs[6][NN*DF];
__device__ float g_tfs[2][NN*64];
__device__ float g_cfs[2][NN*64];
__device__ float g_H1s[4][NN*DF];
__device__ float g_Zs[3][NN*DF];
__device__ float g_Wh1F[NN*DF];
__device__ float g_ArF[NN*DF];
__device__ float g_BrF[NN*DF];
__device__ float g_e0[NN], g_e1[NN];
__device__ float g_P[NN*NN];
__device__ float g_u[DF];
__device__ float g_red[256];
__device__ float g_MS[2];
__device__ float g_s2[NN*NN];
__device__ float g_part[512*DF];
__device__ float g_zH2[DF];
__device__ float g_H3[NN*64];
__device__ int   g_i0[NN], g_i1[NN];
__device__ float g_H4v[64];
__device__ unsigned g_pcnt = 0;

// ---------------- double-buffered 64x64 GEMM tile (f32x2) ----------------
template <bool BNN, class AL4, class BL4>
__device__ __forceinline__ void gemmDB(
    float* smbase, AL4 ldA4, BL4 ldB4,
    int K0, int K1, int m0, int n0, float* __restrict__ C, int ldc)
{
    float (*sA)[16][68] = (float(*)[16][68])smbase;
    float (*sB)[16][68] = (float(*)[16][68])(smbase + 2 * 16 * 68);
    int tid = threadIdx.x, tx = tid & 15, ty = tid >> 4;
    int lr = tid >> 2, lkq = (tid & 3) << 2;
    int kb = tid >> 4, nb4 = (tid & 15) << 2;

    u64 acc[4][2] = {};
    float4 aR = ldA4(m0 + lr, K0 + lkq);
    float4 bR = BNN ? ldB4(n0 + nb4, K0 + kb) : ldB4(n0 + lr, K0 + lkq);
    int nIt = (K1 - K0 + 15) >> 4;
    int buf = 0;
    for (int s = 0; s < nIt; s++) {
        sA[buf][lkq + 0][lr] = aR.x; sA[buf][lkq + 1][lr] = aR.y;
        sA[buf][lkq + 2][lr] = aR.z; sA[buf][lkq + 3][lr] = aR.w;
        if (BNN) {
            *(float4*)&sB[buf][kb][nb4] = bR;
        } else {
            sB[buf][lkq + 0][lr] = bR.x; sB[buf][lkq + 1][lr] = bR.y;
            sB[buf][lkq + 2][lr] = bR.z; sB[buf][lkq + 3][lr] = bR.w;
        }
        __syncthreads();
        if (s + 1 < nIt) {
            int kc = K0 + (s + 1) * 16;
            aR = ldA4(m0 + lr, kc + lkq);
            bR = BNN ? ldB4(n0 + nb4, kc + kb) : ldB4(n0 + lr, kc + lkq);
        }
#pragma unroll
        for (int kk = 0; kk < 16; kk++) {
            float4 av = *(const float4*)&sA[buf][kk][ty << 2];
            ulonglong2 bv = *(const ulonglong2*)&sB[buf][kk][tx << 2];
            u64 a0 = pk2(av.x), a1 = pk2(av.y), a2 = pk2(av.z), a3 = pk2(av.w);
            acc[0][0] = ffma2(a0, bv.x, acc[0][0]); acc[0][1] = ffma2(a0, bv.y, acc[0][1]);
            acc[1][0] = ffma2(a1, bv.x, acc[1][0]); acc[1][1] = ffma2(a1, bv.y, acc[1][1]);
            acc[2][0] = ffma2(a2, bv.x, acc[2][0]); acc[2][1] = ffma2(a2, bv.y, acc[2][1]);
            acc[3][0] = ffma2(a3, bv.x, acc[3][0]); acc[3][1] = ffma2(a3, bv.y, acc[3][1]);
        }
        buf ^= 1;
    }
#pragma unroll
    for (int i = 0; i < 4; i++)
#pragma unroll
        for (int p = 0; p < 2; p++) {
            float2 v = unpk(acc[i][p]);
            int gm = m0 + ty * 4 + i, gn = n0 + tx * 4 + 2 * p;
            C[gm * ldc + gn] = v.x;
            C[gm * ldc + gn + 1] = v.y;
        }
}

// ---------------- prep: neighbors + u + e0/e1 via weight-space GEMV ----------------
__global__ __launch_bounds__(256) void prep_k(const int* __restrict__ adj,
                                              const float* __restrict__ V,
                                              const float* __restrict__ W1,
                                              const float* __restrict__ sa0,
                                              const float* __restrict__ sa1,
                                              const float* __restrict__ ce_w2,
                                              const float* __restrict__ ca0,
                                              const float* __restrict__ ca1)
{
    int b = blockIdx.x, tid = threadIdx.x;
    if (b < 64) {
        int w = tid >> 5, lane = tid & 31;
        int row = b * 8 + w;
        int a = -1, c = -1;
        for (int l = 0; l < 16; l++) {
            int v = adj[row * NN + l * 32 + lane];
            unsigned mask = __ballot_sync(0xffffffffu, v == 1);
            if (mask) {
                if (a < 0) {
                    a = l * 32 + __ffs(mask) - 1;
                    unsigned m2 = mask & (mask - 1);
                    if (m2) c = l * 32 + __ffs(m2) - 1;
                } else {
                    c = l * 32 + __ffs(mask) - 1;
                }
                if (c >= 0) break;
            }
        }
        if (lane == 0) { g_i0[row] = (a < 0) ? NN : a; g_i1[row] = (c < 0) ? NN : c; }
    } else if (b == 64) {
        __shared__ float sc[64];
        if (tid < 64) sc[tid] = ca0[tid] + ca1[tid];
        __syncthreads();
        float acc = 0.f;
#pragma unroll 8
        for (int d = 0; d < 64; d++) acc += ce_w2[d * 256 + tid] * sc[d];
        g_u[tid] = acc;
    } else {
        // w0[k] = sum_d W1[d,k]*sa0[d]; w1 likewise; then e0 = V@w0, e1 = V@w1
        __shared__ float w0[256], w1[256];
        float s0 = 0.f, s1 = 0.f;
        for (int d = 0; d < 256; d++) {
            float wv = W1[d * 256 + tid];
            s0 = fmaf(wv, sa0[d], s0);
            s1 = fmaf(wv, sa1[d], s1);
        }
        w0[tid] = s0; w1[tid] = s1;
        __syncthreads();
#pragma unroll
        for (int rr = 0; rr < 2; rr++) {
            int i = tid + rr * 256;
            const float* vr = V + i * 256;
            float e0 = 0.f, e1 = 0.f;
#pragma unroll 8
            for (int k = 0; k < 256; k++) {
                float vv = vr[k];
                e0 = fmaf(vv, w0[k], e0);
                e1 = fmaf(vv, w1[k], e1);
            }
            g_e0[i] = e0; g_e1[i] = e1;
        }
    }
}

// ---------------- phase A: first-layer GEMMs (512) + gatP (512) = 1024 blocks ----------------
__global__ __launch_bounds__(256, 4) void phaseA_k(
    const float* __restrict__ V, const float* __restrict__ prev,
    const int* __restrict__ adj,
    const float* __restrict__ W1,
    const float* __restrict__ ce_w1,
    const float* __restrict__ te_w1,
    const float* __restrict__ pe_w1)
{
    extern __shared__ float smx[];
    int b = blockIdx.x, tid = threadIdx.x;
    auto ldV = [&](int i, int k4) { return *(const float4*)&V[i * 256 + k4]; };
    if (b < 64) {
        int c = b >> 5, t = b & 31;
        auto ldB = [&](int n, int k4) { return *(const float4*)&W1[n * 256 + k4]; };
        gemmDB<false>(smx, ldV, ldB, c * 128, c * 128 + 128,
                      (t >> 2) * 64, (t & 3) * 64, g_Wh1s[c], 256);
    } else if (b < 128) {
        b -= 64; int c = b >> 5, t = b & 31;
        auto ldB = [&](int n, int k4) { return *(const float4*)&ce_w1[n * 512 + k4]; };
        gemmDB<false>(smx, ldV, ldB, c * 128, c * 128 + 128,
                      (t >> 2) * 64, (t & 3) * 64, g_Ars[c], 256);
    } else if (b < 192) {
        b -= 128; int c = b >> 5, t = b & 31;
        auto ldB = [&](int n, int k4) { return *(const float4*)&ce_w1[n * 512 + 256 + k4]; };
        gemmDB<false>(smx, ldV, ldB, c * 128, c * 128 + 128,
                      (t >> 2) * 64, (t & 3) * 64, g_Brs[c], 256);
    } else if (b < 320) {
        b -= 192; int c = b >> 5, t = b & 31;
        auto ldA = [&](int i, int k4) {
            return (k4 < 256) ? *(const float4*)&V[i * 256 + k4]
                              : *(const float4*)&prev[i * 256 + k4 - 256];
        };
        auto ldB = [&](int n, int k4) { return *(const float4*)&te_w1[n * 512 + k4]; };
        gemmDB<false>(smx, ldA, ldB, c * 128, c * 128 + 128,
                      (t >> 2) * 64, (t & 3) * 64, g_hidTs[c], 256);
    } else if (b < 512) {
        b -= 320; int c = b >> 5, t = b & 31;
        auto ldA = [&](int i, int k4) -> float4 {
            if (k4 < 256) return *(const float4*)&V[i * 256 + k4];
            int i1 = g_i1[i];
            if (i1 >= NN) return make_float4(0.f, 0.f, 0.f, 0.f);
            if (k4 < 512) return *(const float4*)&V[min(g_i0[i], NN - 1) * 256 + (k4 - 256)];
            return *(const float4*)&V[min(i1, NN - 1) * 256 + (k4 - 512)];
        };
        auto ldB = [&](int n, int k4) { return *(const float4*)&pe_w1[n * 768 + k4]; };
        gemmDB<false>(smx, ldA, ldB, c * 128, c * 128 + 128,
                      (t >> 2) * 64, (t & 3) * 64, g_hidPs[c], 256);
    } else {
        // gatP row softmax
        float* r1 = smx;
        float* r2 = smx + 64;
        int i = b - 512;
        float e0i = g_e0[i];
        float sl[2];
        float m = -3.402823466e38f;
#pragma unroll
        for (int s = 0; s < 2; s++) {
            int j = tid + s * 256;
            float v = (adj[i * NN + j] != 0) ? (e0i + g_e1[j]) : -INFINITY;
            sl[s] = v;
            m = fmaxf(m, v);
        }
        int lane = tid & 31, w = tid >> 5;
#pragma unroll
        for (int o = 16; o > 0; o >>= 1) m = fmaxf(m, __shfl_xor_sync(0xffffffffu, m, o));
        if (lane == 0) r1[w] = m;
        __syncthreads();
        m = fmaxf(fmaxf(fmaxf(r1[0], r1[1]), fmaxf(r1[2], r1[3])),
                  fmaxf(fmaxf(r1[4], r1[5]), fmaxf(r1[6], r1[7])));
        float e[2];
        float sum = 0.f;
#pragma unroll
        for (int s = 0; s < 2; s++) { e[s] = __expf(sl[s] - m); sum += e[s]; }
#pragma unroll
        for (int o = 16; o > 0; o >>= 1) sum += __shfl_xor_sync(0xffffffffu, sum, o);
        if (lane == 0) r2[w] = sum;
        __syncthreads();
        sum = r2[0] + r2[1] + r2[2] + r2[3] + r2[4] + r2[5] + r2[6] + r2[7];
        float inv = 1.f / sum;
#pragma unroll
        for (int s = 0; s < 2; s++) g_P[i * NN + tid + s * 256] = e[s] * inv;
    }
}

// ---------------- phase 2a: pair_score(+smax_final last-block) + tf + cf + finish (208) ----------------
__global__ __launch_bounds__(256, 3) void phase2a_k(
    const float* __restrict__ ce_b1,
    const float* __restrict__ te_w2, const float* __restrict__ te_b1,
    const float* __restrict__ pe_w2, const float* __restrict__ pe_b1)
{
    extern __shared__ float smx[];
    char* s_raw = (char*)smx;
    int tid = threadIdx.x;
    int b = blockIdx.x;
    if (b < 128) {
        float (*sA)[16][68] = (float(*)[16][68])s_raw;          // 8704 B
        u64 (*sB2)[16][16] = (u64(*)[16][16])(s_raw + 8704);    // 4096 B
        u64 (*su2)[16]     = (u64(*)[16])(s_raw + 12800);       // 256 B
        float* cAs = (float*)(s_raw + 13056);                   // 256 B
        float* cBs = (float*)(s_raw + 13312);                   // 128 B
        float* rm  = (float*)(s_raw + 13440);                   // 1024 B
        float* rs  = (float*)(s_raw + 14464);                   // 1024 B
        int tx = tid & 15, ty = tid >> 4;
        int ib = (b >> 4) * 64, jb = (b & 15) * 32;
        int w = tid >> 5, lane = tid & 31;

#pragma unroll
        for (int r = 0; r < 8; r++) {
            int i = ib + w * 8 + r;
            float s = 0.f;
#pragma unroll
            for (int t = 0; t < 8; t++) {
                int k = lane + t * 32;
                float a = g_Ars[0][i * 256 + k] + g_Ars[1][i * 256 + k] + ce_b1[k];
                s += a * (0.5f * g_u[k]);
            }
#pragma unroll
            for (int o = 16; o > 0; o >>= 1) s += __shfl_down_sync(0xffffffffu, s, o);
            if (lane == 0) cAs[w * 8 + r] = s;
        }
        if (w < 4) {
#pragma unroll
            for (int r = 0; r < 8; r++) {
                int j = jb + w * 8 + r;
                float s = 0.f;
#pragma unroll
                for (int t = 0; t < 8; t++) {
                    int k = lane + t * 32;
                    float bb = g_Brs[0][j * 256 + k] + g_Brs[1][j * 256 + k];
                    s += bb * (0.5f * g_u[k]);
                }
#pragma unroll
                for (int o = 16; o > 0; o >>= 1) s += __shfl_down_sync(0xffffffffu, s, o);
                if (lane == 0) cBs[w * 8 + r] = s;
            }
        }

        int lr = tid >> 2, lkq = (tid & 3) << 2;
        int bk = tid & 15, jp = tid >> 4;
        auto ldA = [&](int kc) {
            int g = (ib + lr) * 256 + kc + lkq;
            float4 a0 = *(const float4*)&g_Ars[0][g];
            float4 a1 = *(const float4*)&g_Ars[1][g];
            float4 bb = *(const float4*)&ce_b1[kc + lkq];
            return make_float4(a0.x + a1.x + bb.x, a0.y + a1.y + bb.y,
                               a0.z + a1.z + bb.z, a0.w + a1.w + bb.w);
        };
        auto ldB = [&](int kc) {
            int r0 = (jb + 2 * jp) * 256 + kc + bk;
            int r1 = r0 + 256;
            float b0 = g_Brs[0][r0] + g_Brs[1][r0];
            float b1 = g_Brs[0][r1] + g_Brs[1][r1];
            return pk2b(b0, b1);
        };
        u64 acc[4] = {};
        float4 aR = ldA(0);
        u64 bR = ldB(0);
        float suR = (tid < 16) ? 0.5f * g_u[tid] : 0.f;
        int buf = 0;
        for (int s = 0; s < 16; s++) {
            sA[buf][lkq + 0][lr] = aR.x; sA[buf][lkq + 1][lr] = aR.y;
            sA[buf][lkq + 2][lr] = aR.z; sA[buf][lkq + 3][lr] = aR.w;
            sB2[buf][bk][jp] = bR;
            if (tid < 16) su2[buf][tid] = pk2(suR);
            __syncthreads();
            if (s + 1 < 16) {
                int kc = (s + 1) * 16;
                aR = ldA(kc);
                bR = ldB(kc);
                if (tid < 16) suR = 0.5f * g_u[kc + tid];
            }
#pragma unroll
            for (int kk = 0; kk < 16; kk++) {
                float4 av = *(const float4*)&sA[buf][kk][ty << 2];
                u64 b2 = sB2[buf][kk][tx];
                u64 uu = su2[buf][kk];
                u64 t0 = fadd2(pk2(av.x), b2) & ABS2;
                u64 t1 = fadd2(pk2(av.y), b2) & ABS2;
                u64 t2 = fadd2(pk2(av.z), b2) & ABS2;
                u64 t3 = fadd2(pk2(av.w), b2) & ABS2;
                acc[0] = ffma2(t0, uu, acc[0]);
                acc[1] = ffma2(t1, uu, acc[1]);
                acc[2] = ffma2(t2, uu, acc[2]);
                acc[3] = ffma2(t3, uu, acc[3]);
            }
            buf ^= 1;
        }
        int j0 = jb + 2 * tx, j1 = j0 + 1;
        float cb0 = cBs[2 * tx], cb1 = cBs[2 * tx + 1];
        float m = -3.402823466e38f, sum = 0.f;
#pragma unroll
        for (int i = 0; i < 4; i++) {
            int gi = ib + ty * 4 + i;
            float ca = cAs[ty * 4 + i];
            float2 p = unpk(acc[i]);
            float v0 = (gi == j0) ? -INFINITY : (p.x + ca + cb0);
            float v1 = (gi == j1) ? -INFINITY : (p.y + ca + cb1);
            g_s2[gi * NN + j0] = v0;
            g_s2[gi * NN + j1] = v1;
            float nm = fmaxf(m, fmaxf(v0, v1));
            sum = sum * __expf(m - nm) + __expf(v0 - nm) + __expf(v1 - nm);
            m = nm;
        }
        rm[tid] = m; rs[tid] = sum; __syncthreads();
        for (int o = 128; o > 0; o >>= 1) {
            if (tid < o) {
                float m2 = rm[tid + o], s2v = rs[tid + o];
                float M = fmaxf(rm[tid], m2);
                rs[tid] = rs[tid] * __expf(rm[tid] - M) + s2v * __expf(m2 - M);
                rm[tid] = M;
            }
            __syncthreads();
        }
        if (tid == 0) { g_red[2 * b] = rm[0]; g_red[2 * b + 1] = rs[0]; }

        // last pair_score block performs global smax_final
        __shared__ unsigned isLast;
        __threadfence();
        if (tid == 0) isLast = (atomicAdd(&g_pcnt, 1u) == 127u) ? 1u : 0u;
        __syncthreads();
        if (isLast) {
            if (tid == 0) g_pcnt = 0;
            float mm = (tid < 128) ? g_red[2 * tid] : -INFINITY;
            float ss = (tid < 128) ? g_red[2 * tid + 1] : 0.f;
            rm[tid] = mm; rs[tid] = ss; __syncthreads();
            for (int o = 128; o > 0; o >>= 1) {
                if (tid < o) {
                    float m2 = rm[tid + o], s2v = rs[tid + o];
                    float MM = fmaxf(rm[tid], m2);
                    rs[tid] = rs[tid] * __expf(rm[tid] - MM) + s2v * __expf(m2 - MM);
                    rm[tid] = MM;
                }
                __syncthreads();
            }
            if (tid == 0) { g_MS[0] = rm[0]; g_MS[1] = rs[0]; }
        }
    } else if (b < 144) {
        int t = b - 128; int c = t >> 3, mt = t & 7;
        auto ldA = [&](int i, int k4) {
            int g = i * 256 + k4;
            float4 a = *(const float4*)&g_hidTs[0][g];
            float4 bq = *(const float4*)&g_hidTs[1][g];
            float4 cq = *(const float4*)&g_hidTs[2][g];
            float4 dq = *(const float4*)&g_hidTs[3][g];
            float4 bi = *(const float4*)&te_b1[k4];
            return make_float4(fmaxf(a.x + bq.x + cq.x + dq.x + bi.x, 0.f),
                               fmaxf(a.y + bq.y + cq.y + dq.y + bi.y, 0.f),
                               fmaxf(a.z + bq.z + cq.z + dq.z + bi.z, 0.f),
                               fmaxf(a.w + bq.w + cq.w + dq.w + bi.w, 0.f));
        };
        auto ldB = [&](int n, int k4) { return *(const float4*)&te_w2[n * 256 + k4]; };
        gemmDB<false>(smx, ldA, ldB, c * 128, c * 128 + 128, mt * 64, 0, g_tfs[c], 64);
    } else if (b < 160) {
        int t = b - 144; int c = t >> 3, mt = t & 7;
        auto ldA = [&](int i, int k4) {
            int g = i * 256 + k4;
            float4 s0 = *(const float4*)&g_hidPs[0][g];
            float4 s1 = *(const float4*)&g_hidPs[1][g];
            float4 s2q = *(const float4*)&g_hidPs[2][g];
            float4 s3 = *(const float4*)&g_hidPs[3][g];
            float4 s4 = *(const float4*)&g_hidPs[4][g];
            float4 s5 = *(const float4*)&g_hidPs[5][g];
            float4 bi = *(const float4*)&pe_b1[k4];
            return make_float4(
                fmaxf(s0.x + s1.x + s2q.x + s3.x + s4.x + s5.x + bi.x, 0.f),
                fmaxf(s0.y + s1.y + s2q.y + s3.y + s4.y + s5.y + bi.y, 0.f),
                fmaxf(s0.z + s1.z + s2q.z + s3.z + s4.z + s5.z + bi.z, 0.f),
                fmaxf(s0.w + s1.w + s2q.w + s3.w + s4.w + s5.w + bi.w, 0.f));
        };
        auto ldB = [&](int n, int k4) { return *(const float4*)&pe_w2[n * 256 + k4]; };
        gemmDB<false>(smx, ldA, ldB, c * 128, c * 128 + 128, mt * 64, 0, g_cfs[c], 64);
    } else {
        int fb = b - 160;
        int tens = fb >> 4, sub = fb & 15;
        int base = sub * 8192;
#pragma unroll 4
        for (int j = 0; j < 32; j++) {
            int idx = base + j * 256 + tid;
            if (tens == 0) g_Wh1F[idx] = g_Wh1s[0][idx] + g_Wh1s[1][idx];
            else if (tens == 1) g_ArF[idx] = g_Ars[0][idx] + g_Ars[1][idx] + ce_b1[tid];
            else g_BrF[idx] = g_Brs[0][idx] + g_Brs[1][idx];
        }
    }
}

// ---------------- phase 2c: H1 (128) + pair_acc (512) + H3 (1) + H4 (1) = 642 ----------------
__global__ __launch_bounds__(256, 3) void phase2c_k(const float* __restrict__ te_b2,
                                                    const float* __restrict__ pe_b2)
{
    extern __shared__ float smx[];
    char* s_raw = (char*)smx;
    int tid = threadIdx.x;
    int b = blockIdx.x;
    if (b < 128) {
        int c = b >> 5, t = b & 31;
        auto ldA = [&](int i, int k4) { return *(const float4*)&g_P[i * 512 + k4]; };
        auto ldB = [&](int n4, int k) { return *(const float4*)&g_Wh1F[k * 256 + n4]; };
        gemmDB<true>(smx, ldA, ldB, c * 128, c * 128 + 128,
                     (t >> 2) * 64, (t & 3) * 64, g_H1s[c], 256);
    } else if (b < 640) {
        int pb = b - 128;
        int i0 = (pb & 63) * 8;
        int jb = (pb >> 6) * 64;
        float M = g_MS[0], invS = 1.f / g_MS[1];
        u64 (*sw2)[64] = (u64(*)[64])s_raw;
        float* csum = (float*)(s_raw + 4096);
        float* rsum = (float*)(s_raw + 4352);
        u64* cmb   = (u64*)(s_raw + 4608);
        for (int idx = tid; idx < 512; idx += 256) {
            int i = idx >> 6, j = idx & 63;
            float v = __expf(g_s2[(i0 + i) * NN + jb + j] - M) * invS;
            sw2[i][j] = pk2(v);
        }
        __syncthreads();
        if (tid < 64) {
            float s = 0.f;
#pragma unroll
            for (int i = 0; i < 8; i++) s += unpk(sw2[i][tid]).x;
            csum[tid] = 0.5f * s;
        } else if (tid < 72) {
            int i = tid - 64; float s = 0.f;
#pragma unroll 8
            for (int j = 0; j < 64; j++) s += unpk(sw2[i][j]).x;
            rsum[i] = s;
        }
        __syncthreads();
        int kp = tid & 127, half = tid >> 7;
        int k2 = kp * 2;
        u64 a[4];
#pragma unroll
        for (int ii = 0; ii < 4; ii++)
            a[ii] = *(const u64*)&g_ArF[(i0 + half * 4 + ii) * 256 + k2];
        u64 accA0 = 0, accA1 = 0, accA2 = 0, accA3 = 0, accL = 0;
#pragma unroll 4
        for (int jj = 0; jj < 64; jj++) {
            u64 bp = *(const u64*)&g_BrF[(jb + jj) * 256 + k2];
            accL = ffma2(pk2(csum[jj]), bp, accL);
            u64 t0 = fadd2(a[0], bp) & ABS2;
            u64 t1 = fadd2(a[1], bp) & ABS2;
            u64 t2 = fadd2(a[2], bp) & ABS2;
            u64 t3 = fadd2(a[3], bp) & ABS2;
            accA0 = ffma2(sw2[half * 4 + 0][jj], t0, accA0);
            accA1 = ffma2(sw2[half * 4 + 1][jj], t1, accA1);
            accA2 = ffma2(sw2[half * 4 + 2][jj], t2, accA2);
            accA3 = ffma2(sw2[half * 4 + 3][jj], t3, accA3);
        }
#pragma unroll
        for (int ii = 0; ii < 4; ii++)
            accL = ffma2(pk2(rsum[half * 4 + ii]), a[ii], accL);
        u64 tot = fadd2(fadd2(fadd2(accA0, accA1), fadd2(accA2, accA3)), accL);
        if (half == 1) cmb[kp] = tot;
        __syncthreads();
        if (half == 0) {
            float2 t0 = unpk(tot), t1 = unpk(cmb[kp]);
            g_part[pb * 256 + k2]     = 0.5f * (t0.x + t1.x);
            g_part[pb * 256 + k2 + 1] = 0.5f * (t0.y + t1.y);
        }
    } else if (b == 640) {
        // H3 prefix mean
        float* r1 = (float*)s_raw;
        int t = tid & 63, s = tid >> 6;
        float bias = te_b2[t];
        int i0 = s * 128;
        float p0 = 0.f, p1 = 0.f, p2 = 0.f, p3 = 0.f;
#pragma unroll 8
        for (int i = i0; i < i0 + 128; i += 4) {
            p0 += g_tfs[0][i * 64 + t] + g_tfs[1][i * 64 + t];
            p1 += g_tfs[0][(i+1) * 64 + t] + g_tfs[1][(i+1) * 64 + t];
            p2 += g_tfs[0][(i+2) * 64 + t] + g_tfs[1][(i+2) * 64 + t];
            p3 += g_tfs[0][(i+3) * 64 + t] + g_tfs[1][(i+3) * 64 + t];
        }
        r1[s * 64 + t] = p0 + p1 + p2 + p3 + 128.f * bias;
        __syncthreads();
        float acc = 0.f;
        for (int q = 0; q < s; q++) acc += r1[q * 64 + t];
#pragma unroll 16
        for (int i = i0; i < i0 + 128; i++) {
            acc += g_tfs[0][i * 64 + t] + g_tfs[1][i * 64 + t] + bias;
            g_H3[i * 64 + t] = acc / (float)(i + 1);
        }
    } else {
        // H4v
        float* r1 = (float*)s_raw;
        int t = tid & 63, s = tid >> 6;
        float bias = pe_b2[t];
        int i0 = s * 128;
        float p0 = 0.f, p1 = 0.f;
#pragma unroll 8
        for (int i = i0; i < i0 + 128; i += 2) {
            p0 += g_cfs[0][i * 64 + t] + g_cfs[1][i * 64 + t];
            p1 += g_cfs[0][(i+1) * 64 + t] + g_cfs[1][(i+1) * 64 + t];
        }
        r1[s * 64 + t] = p0 + p1 + 128.f * bias;
        __syncthreads();
        if (s == 0) g_H4v[t] = r1[t] + r1[64 + t] + r1[128 + t] + r1[192 + t];
    }
}

// ---------------- phase Z (97 blocks; block 96 = h2+zH2) ----------------
__global__ __launch_bounds__(256, 4) void phaseZ_k(const float* __restrict__ W2,
                                                   const float* __restrict__ ce_w2,
                                                   const float* __restrict__ ce_b2)
{
    extern __shared__ float smx[];
    int b = blockIdx.x, tid = threadIdx.x;
    auto ldB = [&](int n, int k4) {
        float4 r;
        const float* row = W2 + n * 385;
        r.x = (k4     < 385) ? row[k4]     : 0.f;
        r.y = (k4 + 1 < 385) ? row[k4 + 1] : 0.f;
        r.z = (k4 + 2 < 385) ? row[k4 + 2] : 0.f;
        r.w = (k4 + 3 < 385) ? row[k4 + 3] : 0.f;
        return r;
    };
    if (b < 64) {
        int c = b >> 5, t = b & 31;
        auto ldA = [&](int i, int k4) {
            int g = i * 256 + k4;
            float4 s0 = *(const float4*)&g_H1s[0][g];
            float4 s1 = *(const float4*)&g_H1s[1][g];
            float4 s2q = *(const float4*)&g_H1s[2][g];
            float4 s3 = *(const float4*)&g_H1s[3][g];
            return make_float4(s0.x + s1.x + s2q.x + s3.x, s0.y + s1.y + s2q.y + s3.y,
                               s0.z + s1.z + s2q.z + s3.z, s0.w + s1.w + s2q.w + s3.w);
        };
        gemmDB<false>(smx, ldA, ldB, c * 128, c * 128 + 128,
                      (t >> 2) * 64, (t & 3) * 64, g_Zs[c], 256);
    } else if (b < 96) {
        // c2: K range [320, 385) -- H3 + H4 column (H2v handled via zH2 in opln)
        int t = b - 64;
        auto ldA = [&](int i, int k4) -> float4 {
            if (k4 < 384) return *(const float4*)&g_H3[i * 64 + (k4 - 320)];
            if (k4 == 384) return make_float4((i < 64) ? g_H4v[i] : 0.f, 0.f, 0.f, 0.f);
            return make_float4(0.f, 0.f, 0.f, 0.f);
        };
        gemmDB<false>(smx, ldA, ldB, 320, 385,
                      (t >> 2) * 64, (t & 3) * 64, g_Zs[2], 256);
    } else {
        // h2: gv colsum -> H2v -> zH2
        float* gv = smx;
        float* red = smx + 256;
        float* h2v = smx + 512;
        float acc = 0.f;
#pragma unroll 8
        for (int r = 0; r < 512; r++) acc += g_part[r * 256 + tid];
        gv[tid] = acc;
        __syncthreads();
        int d = tid >> 2, q = tid & 3;
        float p = 0.f;
#pragma unroll 16
        for (int k = q * 64; k < q * 64 + 64; k++) p += ce_w2[d * 256 + k] * gv[k];
        red[tid] = p;
        __syncthreads();
        if (q == 0) h2v[d] = red[tid] + red[tid + 1] + red[tid + 2] + red[tid + 3] + ce_b2[d];
        __syncthreads();
        // zH2[n] = sum_d h2v[d] * W2[n, 256+d]
        float z = 0.f;
        const float* wrow = W2 + tid * 385 + 256;
#pragma unroll 8
        for (int dd = 0; dd < 64; dd++) z = fmaf(h2v[dd], wrow[dd], z);
        g_zH2[tid] = z;
    }
}

// ---------------- opln (128 blocks) ----------------
__global__ __launch_bounds__(256) void opln_k(const float* __restrict__ op_w,
                                              const float* __restrict__ op_b,
                                              const float* __restrict__ ln_g,
                                              const float* __restrict__ ln_b,
                                              float* __restrict__ out)
{
    __shared__ __align__(16) float sA[16][4];
    __shared__ float sB[16][256];
    __shared__ __align__(16) float4 red[256];
    int tid = threadIdx.x;
    int m0 = blockIdx.x * 4;
    float acc[4] = {};
    for (int kc = 0; kc < 256; kc += 16) {
        if (tid < 64) {
            int r = tid >> 4, k = tid & 15;
            int g = (m0 + r) * 256 + kc + k;
            sA[k][r] = g_Zs[0][g] + g_Zs[1][g] + g_Zs[2][g] + g_zH2[kc + k];
        }
#pragma unroll
        for (int s = 0; s < 16; s++) {
            int idx = tid + s * 256;
            int n = idx >> 4, k = idx & 15;
            sB[k][n] = op_w[n * 256 + kc + k];
        }
        __syncthreads();
#pragma unroll
        for (int kk = 0; kk < 16; kk++) {
            float4 a = *(const float4*)&sA[kk][0];
            float bv = sB[kk][tid];
            acc[0] = fmaf(a.x, bv, acc[0]);
            acc[1] = fmaf(a.y, bv, acc[1]);
            acc[2] = fmaf(a.z, bv, acc[2]);
            acc[3] = fmaf(a.w, bv, acc[3]);
        }
        __syncthreads();
    }
    float bias = op_b[tid];
#pragma unroll
    for (int r = 0; r < 4; r++) acc[r] += bias;
    red[tid] = make_float4(acc[0], acc[1], acc[2], acc[3]);
    __syncthreads();
    for (int o = 128; o > 0; o >>= 1) {
        if (tid < o) {
            float4 x = red[tid], y = red[tid + o];
            red[tid] = make_float4(x.x + y.x, x.y + y.y, x.z + y.z, x.w + y.w);
        }
        __syncthreads();
    }
    float4 mu4 = red[0];
    __syncthreads();
    float mu[4] = { mu4.x * (1.f/256.f), mu4.y * (1.f/256.f), mu4.z * (1.f/256.f), mu4.w * (1.f/256.f) };
    float d0 = acc[0] - mu[0], d1 = acc[1] - mu[1], d2 = acc[2] - mu[2], d3 = acc[3] - mu[3];
    red[tid] = make_float4(d0 * d0, d1 * d1, d2 * d2, d3 * d3);
    __syncthreads();
    for (int o = 128; o > 0; o >>= 1) {
        if (tid < o) {
            float4 x = red[tid], y = red[tid + o];
            red[tid] = make_float4(x.x + y.x, x.y + y.y, x.z + y.z, x.w + y.w);
        }
        __syncthreads();
    }
    float4 v4 = red[0];
    float inv[4] = { rsqrtf(v4.x * (1.f/256.f) + 1e-5f), rsqrtf(v4.y * (1.f/256.f) + 1e-5f),
                     rsqrtf(v4.z * (1.f/256.f) + 1e-5f), rsqrtf(v4.w * (1.f/256.f) + 1e-5f) };
    float g = ln_g[tid], bb = ln_b[tid];
    float dd[4] = { d0, d1, d2, d3 };
#pragma unroll
    for (int r = 0; r < 4; r++) {
        float y = dd[r] * inv[r] * g + bb;
        out[(m0 + r) * 256 + tid] = (y > 0.f) ? y : expm1f(y);
    }
}

// ---------------- host ----------------
extern "C" void kernel_launch(void* const* d_in, const int* in_sizes, int n_in,
                              void* d_out, int out_size)
{
    const float* V       = (const float*)d_in[0];
    const int*   adj     = (const int*)d_in[1];
    const float* prev    = (const float*)d_in[2];
    const float* W1      = (const float*)d_in[3];
    const float* sa0     = (const float*)d_in[4];
    const float* sa1     = (const float*)d_in[5];
    const float* ce_w1   = (const float*)d_in[6];
    const float* ce_b1   = (const float*)d_in[7];
    const float* ce_w2   = (const float*)d_in[8];
    const float* ce_b2   = (const float*)d_in[9];
    const float* ca0     = (const float*)d_in[10];
    const float* ca1     = (const float*)d_in[11];
    const float* te_w1   = (const float*)d_in[12];
    const float* te_b1   = (const float*)d_in[13];
    const float* te_w2   = (const float*)d_in[14];
    const float* te_b2   = (const float*)d_in[15];
    const float* pe_w1   = (const float*)d_in[18];
    const float* pe_b1   = (const float*)d_in[19];
    const float* pe_w2   = (const float*)d_in[20];
    const float* pe_b2   = (const float*)d_in[21];
    const float* W2      = (const float*)d_in[24];
    const float* op_w    = (const float*)d_in[25];
    const float* op_b    = (const float*)d_in[26];
    const float* ln_g    = (const float*)d_in[27];
    const float* ln_b    = (const float*)d_in[28];
    float* out = (float*)d_out;

    const int DBSM = 2 * 2 * 16 * 68 * 4;   // 17408 B

    prep_k   <<<66,   256>>>(adj, V, W1, sa0, sa1, ce_w2, ca0, ca1);
    phaseA_k <<<1024, 256, DBSM>>>(V, prev, adj, W1, ce_w1, te_w1, pe_w1);
    phase2a_k<<<208,  256, DBSM>>>(ce_b1, te_w2, te_b1, pe_w2, pe_b1);
    phase2c_k<<<642,  256, DBSM>>>(te_b2, pe_b2);
    phaseZ_k <<<97,   256, DBSM>>>(W2, ce_w2, ce_b2);
    opln_k   <<<128,  256>>>(op_w, op_b, ln_g, ln_b, out);
}

// round 13
// speedup vs baseline: 1.3945x; 1.3945x over previous
#include <cuda_runtime.h>
#include <math.h>

#define NN 512
#define DF 256
typedef unsigned long long u64;

// ---------------- f32x2 helpers ----------------
__device__ __forceinline__ u64 pk2(float x) {
    u64 r; unsigned xi = __float_as_uint(x);
    asm("mov.b64 %0, {%1, %1};" : "=l"(r) : "r"(xi));
    return r;
}
__device__ __forceinline__ u64 pk2b(float lo, float hi) {
    u64 r; unsigned a = __float_as_uint(lo), b = __float_as_uint(hi);
    asm("mov.b64 %0, {%1, %2};" : "=l"(r) : "r"(a), "r"(b));
    return r;
}
__device__ __forceinline__ float2 unpk(u64 v) {
    unsigned a, b;
    asm("mov.b64 {%0, %1}, %2;" : "=r"(a), "=r"(b) : "l"(v));
    return make_float2(__uint_as_float(a), __uint_as_float(b));
}
__device__ __forceinline__ u64 ffma2(u64 a, u64 b, u64 c) {
    u64 r;
    asm("fma.rn.f32x2 %0, %1, %2, %3;" : "=l"(r) : "l"(a), "l"(b), "l"(c));
    return r;
}
__device__ __forceinline__ u64 fadd2(u64 a, u64 b) {
    u64 r;
    asm("add.rn.f32x2 %0, %1, %2;" : "=l"(r) : "l"(a), "l"(b));
    return r;
}
#define ABS2 0x7fffffff7fffffffULL

// ---------------- scratch ----------------
__device__ float g_Wh1s[2][NN*DF];
__device__ float g_Ars[2][NN*DF];
__device__ float g_Brs[2][NN*DF];
__device__ float g_hidTs[4][NN*DF];
__device__ float g_hidPs[6][NN*DF];
__device__ float g_tfs[2][NN*64];
__device__ float g_cfs[2][NN*64];
__device__ float g_H1s[4][NN*DF];
__device__ float g_Zs[3][NN*DF];
__device__ float g_Wh1F[NN*DF];
__device__ float g_ArF[NN*DF];
__device__ float g_BrF[NN*DF];
__device__ float g_e0[NN], g_e1[NN];
__device__ float g_P[NN*NN];
__device__ float g_u[DF];
__device__ float g_red[256];
__device__ float g_MS[2];
__device__ float g_s2[NN*NN];
__device__ float g_part[512*DF];
__device__ float g_zH2[DF];
__device__ float g_H3[NN*64];
__device__ int   g_i0[NN], g_i1[NN];
__device__ float g_H4v[64];

// ---------------- double-buffered 64x64 GEMM tile (f32x2) ----------------
template <bool BNN, class AL4, class BL4>
__device__ __forceinline__ void gemmDB(
    float* smbase, AL4 ldA4, BL4 ldB4,
    int K0, int K1, int m0, int n0, float* __restrict__ C, int ldc)
{
    float (*sA)[16][68] = (float(*)[16][68])smbase;
    float (*sB)[16][68] = (float(*)[16][68])(smbase + 2 * 16 * 68);
    int tid = threadIdx.x, tx = tid & 15, ty = tid >> 4;
    int lr = tid >> 2, lkq = (tid & 3) << 2;
    int kb = tid >> 4, nb4 = (tid & 15) << 2;

    u64 acc[4][2] = {};
    float4 aR = ldA4(m0 + lr, K0 + lkq);
    float4 bR = BNN ? ldB4(n0 + nb4, K0 + kb) : ldB4(n0 + lr, K0 + lkq);
    int nIt = (K1 - K0 + 15) >> 4;
    int buf = 0;
    for (int s = 0; s < nIt; s++) {
        sA[buf][lkq + 0][lr] = aR.x; sA[buf][lkq + 1][lr] = aR.y;
        sA[buf][lkq + 2][lr] = aR.z; sA[buf][lkq + 3][lr] = aR.w;
        if (BNN) {
            *(float4*)&sB[buf][kb][nb4] = bR;
        } else {
            sB[buf][lkq + 0][lr] = bR.x; sB[buf][lkq + 1][lr] = bR.y;
            sB[buf][lkq + 2][lr] = bR.z; sB[buf][lkq + 3][lr] = bR.w;
        }
        __syncthreads();
        if (s + 1 < nIt) {
            int kc = K0 + (s + 1) * 16;
            aR = ldA4(m0 + lr, kc + lkq);
            bR = BNN ? ldB4(n0 + nb4, kc + kb) : ldB4(n0 + lr, kc + lkq);
        }
#pragma unroll
        for (int kk = 0; kk < 16; kk++) {
            float4 av = *(const float4*)&sA[buf][kk][ty << 2];
            ulonglong2 bv = *(const ulonglong2*)&sB[buf][kk][tx << 2];
            u64 a0 = pk2(av.x), a1 = pk2(av.y), a2 = pk2(av.z), a3 = pk2(av.w);
            acc[0][0] = ffma2(a0, bv.x, acc[0][0]); acc[0][1] = ffma2(a0, bv.y, acc[0][1]);
            acc[1][0] = ffma2(a1, bv.x, acc[1][0]); acc[1][1] = ffma2(a1, bv.y, acc[1][1]);
            acc[2][0] = ffma2(a2, bv.x, acc[2][0]); acc[2][1] = ffma2(a2, bv.y, acc[2][1]);
            acc[3][0] = ffma2(a3, bv.x, acc[3][0]); acc[3][1] = ffma2(a3, bv.y, acc[3][1]);
        }
        buf ^= 1;
    }
#pragma unroll
    for (int i = 0; i < 4; i++)
#pragma unroll
        for (int p = 0; p < 2; p++) {
            float2 v = unpk(acc[i][p]);
            int gm = m0 + ty * 4 + i, gn = n0 + tx * 4 + 2 * p;
            C[gm * ldc + gn] = v.x;
            C[gm * ldc + gn + 1] = v.y;
        }
}

// ---------------- prep: neighbor indices (ballot) + u ----------------
__global__ __launch_bounds__(256) void prep_k(const int* __restrict__ adj,
                                              const float* __restrict__ ce_w2,
                                              const float* __restrict__ ca0,
                                              const float* __restrict__ ca1)
{
    int b = blockIdx.x, tid = threadIdx.x;
    if (b < 64) {
        int w = tid >> 5, lane = tid & 31;
        int row = b * 8 + w;
        int a = -1, c = -1;
        for (int l = 0; l < 16; l++) {
            int v = adj[row * NN + l * 32 + lane];
            unsigned mask = __ballot_sync(0xffffffffu, v == 1);
            if (mask) {
                if (a < 0) {
                    a = l * 32 + __ffs(mask) - 1;
                    unsigned m2 = mask & (mask - 1);
                    if (m2) c = l * 32 + __ffs(m2) - 1;
                } else {
                    c = l * 32 + __ffs(mask) - 1;
                }
                if (c >= 0) break;
            }
        }
        if (lane == 0) { g_i0[row] = (a < 0) ? NN : a; g_i1[row] = (c < 0) ? NN : c; }
    } else {
        __shared__ float sc[64];
        if (tid < 64) sc[tid] = ca0[tid] + ca1[tid];
        __syncthreads();
        float acc = 0.f;
#pragma unroll 8
        for (int d = 0; d < 64; d++) acc += ce_w2[d * 256 + tid] * sc[d];
        g_u[tid] = acc;
    }
}

// ---------------- phase A: first-layer GEMMs (512 blocks) ----------------
__global__ __launch_bounds__(256, 4) void phaseA_k(
    const float* __restrict__ V, const float* __restrict__ prev,
    const float* __restrict__ W1,
    const float* __restrict__ ce_w1,
    const float* __restrict__ te_w1,
    const float* __restrict__ pe_w1)
{
    extern __shared__ float smx[];
    int b = blockIdx.x;
    auto ldV = [&](int i, int k4) { return *(const float4*)&V[i * 256 + k4]; };
    if (b < 64) {
        int c = b >> 5, t = b & 31;
        auto ldB = [&](int n, int k4) { return *(const float4*)&W1[n * 256 + k4]; };
        gemmDB<false>(smx, ldV, ldB, c * 128, c * 128 + 128,
                      (t >> 2) * 64, (t & 3) * 64, g_Wh1s[c], 256);
    } else if (b < 128) {
        b -= 64; int c = b >> 5, t = b & 31;
        auto ldB = [&](int n, int k4) { return *(const float4*)&ce_w1[n * 512 + k4]; };
        gemmDB<false>(smx, ldV, ldB, c * 128, c * 128 + 128,
                      (t >> 2) * 64, (t & 3) * 64, g_Ars[c], 256);
    } else if (b < 192) {
        b -= 128; int c = b >> 5, t = b & 31;
        auto ldB = [&](int n, int k4) { return *(const float4*)&ce_w1[n * 512 + 256 + k4]; };
        gemmDB<false>(smx, ldV, ldB, c * 128, c * 128 + 128,
                      (t >> 2) * 64, (t & 3) * 64, g_Brs[c], 256);
    } else if (b < 320) {
        b -= 192; int c = b >> 5, t = b & 31;
        auto ldA = [&](int i, int k4) {
            return (k4 < 256) ? *(const float4*)&V[i * 256 + k4]
                              : *(const float4*)&prev[i * 256 + k4 - 256];
        };
        auto ldB = [&](int n, int k4) { return *(const float4*)&te_w1[n * 512 + k4]; };
        gemmDB<false>(smx, ldA, ldB, c * 128, c * 128 + 128,
                      (t >> 2) * 64, (t & 3) * 64, g_hidTs[c], 256);
    } else {
        b -= 320; int c = b >> 5, t = b & 31;
        auto ldA = [&](int i, int k4) -> float4 {
            if (k4 < 256) return *(const float4*)&V[i * 256 + k4];
            int i1 = g_i1[i];
            if (i1 >= NN) return make_float4(0.f, 0.f, 0.f, 0.f);
            if (k4 < 512) return *(const float4*)&V[min(g_i0[i], NN - 1) * 256 + (k4 - 256)];
            return *(const float4*)&V[min(i1, NN - 1) * 256 + (k4 - 512)];
        };
        auto ldB = [&](int n, int k4) { return *(const float4*)&pe_w1[n * 768 + k4]; };
        gemmDB<false>(smx, ldA, ldB, c * 128, c * 128 + 128,
                      (t >> 2) * 64, (t & 3) * 64, g_hidPs[c], 256);
    }
}

// ---------------- phase 2a: pair_score(db) + e01 + tf + cf + finish (272 blocks) ----------------
__global__ __launch_bounds__(256, 3) void phase2a_k(
    const float* __restrict__ sa0, const float* __restrict__ sa1,
    const float* __restrict__ ce_b1,
    const float* __restrict__ te_w2, const float* __restrict__ te_b1,
    const float* __restrict__ pe_w2, const float* __restrict__ pe_b1)
{
    extern __shared__ float smx[];
    char* s_raw = (char*)smx;
    int tid = threadIdx.x;
    int b = blockIdx.x;
    if (b < 128) {
        // pair_score: 64 i x 32 j tile, K=256, double-buffered.
        float (*sA)[16][68] = (float(*)[16][68])s_raw;          // 8704 B
        u64 (*sB2)[16][16] = (u64(*)[16][16])(s_raw + 8704);    // 4096 B
        u64 (*su2)[16]     = (u64(*)[16])(s_raw + 12800);       // 256 B
        float* cAs = (float*)(s_raw + 13056);                   // 256 B
        float* cBs = (float*)(s_raw + 13312);                   // 128 B
        float* rm  = (float*)(s_raw + 13440);                   // 1024 B
        float* rs  = (float*)(s_raw + 14464);                   // 1024 B
        int tx = tid & 15, ty = tid >> 4;
        int ib = (b >> 4) * 64, jb = (b & 15) * 32;
        int w = tid >> 5, lane = tid & 31;

        // cA / cB rank-1 constants
#pragma unroll
        for (int r = 0; r < 8; r++) {
            int i = ib + w * 8 + r;
            float s = 0.f;
#pragma unroll
            for (int t = 0; t < 8; t++) {
                int k = lane + t * 32;
                float a = g_Ars[0][i * 256 + k] + g_Ars[1][i * 256 + k] + ce_b1[k];
                s += a * (0.5f * g_u[k]);
            }
#pragma unroll
            for (int o = 16; o > 0; o >>= 1) s += __shfl_down_sync(0xffffffffu, s, o);
            if (lane == 0) cAs[w * 8 + r] = s;
        }
        if (w < 4) {
#pragma unroll
            for (int r = 0; r < 8; r++) {
                int j = jb + w * 8 + r;
                float s = 0.f;
#pragma unroll
                for (int t = 0; t < 8; t++) {
                    int k = lane + t * 32;
                    float bb = g_Brs[0][j * 256 + k] + g_Brs[1][j * 256 + k];
                    s += bb * (0.5f * g_u[k]);
                }
#pragma unroll
                for (int o = 16; o > 0; o >>= 1) s += __shfl_down_sync(0xffffffffu, s, o);
                if (lane == 0) cBs[w * 8 + r] = s;
            }
        }

        // double-buffered mainloop
        int lr = tid >> 2, lkq = (tid & 3) << 2;
        int bk = tid & 15, jp = tid >> 4;
        auto ldA = [&](int kc) {
            int g = (ib + lr) * 256 + kc + lkq;
            float4 a0 = *(const float4*)&g_Ars[0][g];
            float4 a1 = *(const float4*)&g_Ars[1][g];
            float4 bb = *(const float4*)&ce_b1[kc + lkq];
            return make_float4(a0.x + a1.x + bb.x, a0.y + a1.y + bb.y,
                               a0.z + a1.z + bb.z, a0.w + a1.w + bb.w);
        };
        auto ldB = [&](int kc) {
            int r0 = (jb + 2 * jp) * 256 + kc + bk;
            int r1 = r0 + 256;
            float b0 = g_Brs[0][r0] + g_Brs[1][r0];
            float b1 = g_Brs[0][r1] + g_Brs[1][r1];
            return pk2b(b0, b1);
        };
        u64 acc[4] = {};
        float4 aR = ldA(0);
        u64 bR = ldB(0);
        float suR = (tid < 16) ? 0.5f * g_u[tid] : 0.f;
        int buf = 0;
        for (int s = 0; s < 16; s++) {
            sA[buf][lkq + 0][lr] = aR.x; sA[buf][lkq + 1][lr] = aR.y;
            sA[buf][lkq + 2][lr] = aR.z; sA[buf][lkq + 3][lr] = aR.w;
            sB2[buf][bk][jp] = bR;
            if (tid < 16) su2[buf][tid] = pk2(suR);
            __syncthreads();
            if (s + 1 < 16) {
                int kc = (s + 1) * 16;
                aR = ldA(kc);
                bR = ldB(kc);
                if (tid < 16) suR = 0.5f * g_u[kc + tid];
            }
#pragma unroll
            for (int kk = 0; kk < 16; kk++) {
                float4 av = *(const float4*)&sA[buf][kk][ty << 2];
                u64 b2 = sB2[buf][kk][tx];
                u64 uu = su2[buf][kk];
                u64 t0 = fadd2(pk2(av.x), b2) & ABS2;
                u64 t1 = fadd2(pk2(av.y), b2) & ABS2;
                u64 t2 = fadd2(pk2(av.z), b2) & ABS2;
                u64 t3 = fadd2(pk2(av.w), b2) & ABS2;
                acc[0] = ffma2(t0, uu, acc[0]);
                acc[1] = ffma2(t1, uu, acc[1]);
                acc[2] = ffma2(t2, uu, acc[2]);
                acc[3] = ffma2(t3, uu, acc[3]);
            }
            buf ^= 1;
        }
        int j0 = jb + 2 * tx, j1 = j0 + 1;
        float cb0 = cBs[2 * tx], cb1 = cBs[2 * tx + 1];
        float m = -3.402823466e38f, sum = 0.f;
#pragma unroll
        for (int i = 0; i < 4; i++) {
            int gi = ib + ty * 4 + i;
            float ca = cAs[ty * 4 + i];
            float2 p = unpk(acc[i]);
            float v0 = (gi == j0) ? -INFINITY : (p.x + ca + cb0);
            float v1 = (gi == j1) ? -INFINITY : (p.y + ca + cb1);
            g_s2[gi * NN + j0] = v0;
            g_s2[gi * NN + j1] = v1;
            float nm = fmaxf(m, fmaxf(v0, v1));
            sum = sum * __expf(m - nm) + __expf(v0 - nm) + __expf(v1 - nm);
            m = nm;
        }
        rm[tid] = m; rs[tid] = sum; __syncthreads();
        for (int o = 128; o > 0; o >>= 1) {
            if (tid < o) {
                float m2 = rm[tid + o], s2v = rs[tid + o];
                float M = fmaxf(rm[tid], m2);
                rs[tid] = rs[tid] * __expf(rm[tid] - M) + s2v * __expf(m2 - M);
                rm[tid] = M;
            }
            __syncthreads();
        }
        if (tid == 0) { g_red[2 * b] = rm[0]; g_red[2 * b + 1] = rs[0]; }
    } else if (b < 192) {
        int eb = b - 128;
        int w = tid >> 5, lane = tid & 31;
        int row = eb * 8 + w;
        float a0 = 0.f, a1 = 0.f;
#pragma unroll
        for (int l = 0; l < 8; l++) {
            int k = lane + l * 32;
            float a = g_Wh1s[0][row * 256 + k] + g_Wh1s[1][row * 256 + k];
            a0 += a * sa0[k];
            a1 += a * sa1[k];
        }
#pragma unroll
        for (int o = 16; o > 0; o >>= 1) {
            a0 += __shfl_down_sync(0xffffffffu, a0, o);
            a1 += __shfl_down_sync(0xffffffffu, a1, o);
        }
        if (lane == 0) { g_e0[row] = a0; g_e1[row] = a1; }
    } else if (b < 208) {
        int t = b - 192; int c = t >> 3, mt = t & 7;
        auto ldA = [&](int i, int k4) {
            int g = i * 256 + k4;
            float4 a = *(const float4*)&g_hidTs[0][g];
            float4 bq = *(const float4*)&g_hidTs[1][g];
            float4 cq = *(const float4*)&g_hidTs[2][g];
            float4 dq = *(const float4*)&g_hidTs[3][g];
            float4 bi = *(const float4*)&te_b1[k4];
            return make_float4(fmaxf(a.x + bq.x + cq.x + dq.x + bi.x, 0.f),
                               fmaxf(a.y + bq.y + cq.y + dq.y + bi.y, 0.f),
                               fmaxf(a.z + bq.z + cq.z + dq.z + bi.z, 0.f),
                               fmaxf(a.w + bq.w + cq.w + dq.w + bi.w, 0.f));
        };
        auto ldB = [&](int n, int k4) { return *(const float4*)&te_w2[n * 256 + k4]; };
        gemmDB<false>(smx, ldA, ldB, c * 128, c * 128 + 128, mt * 64, 0, g_tfs[c], 64);
    } else if (b < 224) {
        int t = b - 208; int c = t >> 3, mt = t & 7;
        auto ldA = [&](int i, int k4) {
            int g = i * 256 + k4;
            float4 s0 = *(const float4*)&g_hidPs[0][g];
            float4 s1 = *(const float4*)&g_hidPs[1][g];
            float4 s2q = *(const float4*)&g_hidPs[2][g];
            float4 s3 = *(const float4*)&g_hidPs[3][g];
            float4 s4 = *(const float4*)&g_hidPs[4][g];
            float4 s5 = *(const float4*)&g_hidPs[5][g];
            float4 bi = *(const float4*)&pe_b1[k4];
            return make_float4(
                fmaxf(s0.x + s1.x + s2q.x + s3.x + s4.x + s5.x + bi.x, 0.f),
                fmaxf(s0.y + s1.y + s2q.y + s3.y + s4.y + s5.y + bi.y, 0.f),
                fmaxf(s0.z + s1.z + s2q.z + s3.z + s4.z + s5.z + bi.z, 0.f),
                fmaxf(s0.w + s1.w + s2q.w + s3.w + s4.w + s5.w + bi.w, 0.f));
        };
        auto ldB = [&](int n, int k4) { return *(const float4*)&pe_w2[n * 256 + k4]; };
        gemmDB<false>(smx, ldA, ldB, c * 128, c * 128 + 128, mt * 64, 0, g_cfs[c], 64);
    } else {
        int fb = b - 224;
        int tens = fb >> 4, sub = fb & 15;
        int base = sub * 8192;
#pragma unroll 4
        for (int j = 0; j < 32; j++) {
            int idx = base + j * 256 + tid;
            if (tens == 0) g_Wh1F[idx] = g_Wh1s[0][idx] + g_Wh1s[1][idx];
            else if (tens == 1) g_ArF[idx] = g_Ars[0][idx] + g_Ars[1][idx] + ce_b1[tid];
            else g_BrF[idx] = g_Brs[0][idx] + g_Brs[1][idx];
        }
    }
}

// ---------------- phase 2b: smax_final + H3 + H4 + gatP (515 blocks) ----------------
__global__ __launch_bounds__(256) void phase2b_k(const int* __restrict__ adj,
                                                 const float* __restrict__ te_b2,
                                                 const float* __restrict__ pe_b2)
{
    __shared__ float r1[256], r2[256];
    int b = blockIdx.x, tid = threadIdx.x;
    if (b == 0) {
        float m = (tid < 128) ? g_red[2 * tid] : -INFINITY;
        float s = (tid < 128) ? g_red[2 * tid + 1] : 0.f;
        r1[tid] = m; r2[tid] = s; __syncthreads();
        for (int o = 128; o > 0; o >>= 1) {
            if (tid < o) {
                float m2 = r1[tid + o], s2v = r2[tid + o];
                float MM = fmaxf(r1[tid], m2);
                r2[tid] = r2[tid] * __expf(r1[tid] - MM) + s2v * __expf(m2 - MM);
                r1[tid] = MM;
            }
            __syncthreads();
        }
        if (tid == 0) { g_MS[0] = r1[0]; g_MS[1] = r2[0]; }
    } else if (b == 1) {
        int t = tid & 63, s = tid >> 6;
        float bias = te_b2[t];
        int i0 = s * 128;
        float p0 = 0.f, p1 = 0.f, p2 = 0.f, p3 = 0.f;
#pragma unroll 8
        for (int i = i0; i < i0 + 128; i += 4) {
            p0 += g_tfs[0][i * 64 + t] + g_tfs[1][i * 64 + t];
            p1 += g_tfs[0][(i+1) * 64 + t] + g_tfs[1][(i+1) * 64 + t];
            p2 += g_tfs[0][(i+2) * 64 + t] + g_tfs[1][(i+2) * 64 + t];
            p3 += g_tfs[0][(i+3) * 64 + t] + g_tfs[1][(i+3) * 64 + t];
        }
        r1[s * 64 + t] = p0 + p1 + p2 + p3 + 128.f * bias;
        __syncthreads();
        float acc = 0.f;
        for (int q = 0; q < s; q++) acc += r1[q * 64 + t];
#pragma unroll 16
        for (int i = i0; i < i0 + 128; i++) {
            acc += g_tfs[0][i * 64 + t] + g_tfs[1][i * 64 + t] + bias;
            g_H3[i * 64 + t] = acc / (float)(i + 1);
        }
    } else if (b == 2) {
        int t = tid & 63, s = tid >> 6;
        float bias = pe_b2[t];
        int i0 = s * 128;
        float p0 = 0.f, p1 = 0.f;
#pragma unroll 8
        for (int i = i0; i < i0 + 128; i += 2) {
            p0 += g_cfs[0][i * 64 + t] + g_cfs[1][i * 64 + t];
            p1 += g_cfs[0][(i+1) * 64 + t] + g_cfs[1][(i+1) * 64 + t];
        }
        r1[s * 64 + t] = p0 + p1 + 128.f * bias;
        __syncthreads();
        if (s == 0) g_H4v[t] = r1[t] + r1[64 + t] + r1[128 + t] + r1[192 + t];
    } else {
        int i = b - 3;
        float e0i = g_e0[i];
        float sl[2];
        float m = -3.402823466e38f;
#pragma unroll
        for (int s = 0; s < 2; s++) {
            int j = tid + s * 256;
            float v = (adj[i * NN + j] != 0) ? (e0i + g_e1[j]) : -INFINITY;
            sl[s] = v;
            m = fmaxf(m, v);
        }
        int lane = tid & 31, w = tid >> 5;
#pragma unroll
        for (int o = 16; o > 0; o >>= 1) m = fmaxf(m, __shfl_xor_sync(0xffffffffu, m, o));
        if (lane == 0) r1[w] = m;
        __syncthreads();
        m = fmaxf(fmaxf(fmaxf(r1[0], r1[1]), fmaxf(r1[2], r1[3])),
                  fmaxf(fmaxf(r1[4], r1[5]), fmaxf(r1[6], r1[7])));
        float e[2];
        float sum = 0.f;
#pragma unroll
        for (int s = 0; s < 2; s++) { e[s] = __expf(sl[s] - m); sum += e[s]; }
#pragma unroll
        for (int o = 16; o > 0; o >>= 1) sum += __shfl_xor_sync(0xffffffffu, sum, o);
        if (lane == 0) r2[w] = sum;
        __syncthreads();
        sum = r2[0] + r2[1] + r2[2] + r2[3] + r2[4] + r2[5] + r2[6] + r2[7];
        float inv = 1.f / sum;
#pragma unroll
        for (int s = 0; s < 2; s++) g_P[i * NN + tid + s * 256] = e[s] * inv;
    }
}

// ---------------- phase 2c: H1 chunks (128) + pair_acc abs-trick (512) ----------------
__global__ __launch_bounds__(256, 3) void phase2c_k()
{
    extern __shared__ float smx[];
    char* s_raw = (char*)smx;
    int tid = threadIdx.x;
    int b = blockIdx.x;
    if (b < 128) {
        int c = b >> 5, t = b & 31;
        auto ldA = [&](int i, int k4) { return *(const float4*)&g_P[i * 512 + k4]; };
        auto ldB = [&](int n4, int k) { return *(const float4*)&g_Wh1F[k * 256 + n4]; };
        gemmDB<true>(smx, ldA, ldB, c * 128, c * 128 + 128,
                     (t >> 2) * 64, (t & 3) * 64, g_H1s[c], 256);
    } else {
        int pb = b - 128;
        int i0 = (pb & 63) * 8;
        int jb = (pb >> 6) * 64;
        float M = g_MS[0], invS = 1.f / g_MS[1];
        u64 (*sw2)[64] = (u64(*)[64])s_raw;
        float* csum = (float*)(s_raw + 4096);
        float* rsum = (float*)(s_raw + 4352);
        u64* cmb   = (u64*)(s_raw + 4608);
        for (int idx = tid; idx < 512; idx += 256) {
            int i = idx >> 6, j = idx & 63;
            float v = __expf(g_s2[(i0 + i) * NN + jb + j] - M) * invS;
            sw2[i][j] = pk2(v);
        }
        __syncthreads();
        if (tid < 64) {
            float s = 0.f;
#pragma unroll
            for (int i = 0; i < 8; i++) s += unpk(sw2[i][tid]).x;
            csum[tid] = 0.5f * s;
        } else if (tid < 72) {
            int i = tid - 64; float s = 0.f;
#pragma unroll 8
            for (int j = 0; j < 64; j++) s += unpk(sw2[i][j]).x;
            rsum[i] = s;
        }
        __syncthreads();
        int kp = tid & 127, half = tid >> 7;
        int k2 = kp * 2;
        u64 a[4];
#pragma unroll
        for (int ii = 0; ii < 4; ii++)
            a[ii] = *(const u64*)&g_ArF[(i0 + half * 4 + ii) * 256 + k2];
        u64 accA0 = 0, accA1 = 0, accA2 = 0, accA3 = 0, accL = 0;
#pragma unroll 4
        for (int jj = 0; jj < 64; jj++) {
            u64 bp = *(const u64*)&g_BrF[(jb + jj) * 256 + k2];
            accL = ffma2(pk2(csum[jj]), bp, accL);
            u64 t0 = fadd2(a[0], bp) & ABS2;
            u64 t1 = fadd2(a[1], bp) & ABS2;
            u64 t2 = fadd2(a[2], bp) & ABS2;
            u64 t3 = fadd2(a[3], bp) & ABS2;
            accA0 = ffma2(sw2[half * 4 + 0][jj], t0, accA0);
            accA1 = ffma2(sw2[half * 4 + 1][jj], t1, accA1);
            accA2 = ffma2(sw2[half * 4 + 2][jj], t2, accA2);
            accA3 = ffma2(sw2[half * 4 + 3][jj], t3, accA3);
        }
#pragma unroll
        for (int ii = 0; ii < 4; ii++)
            accL = ffma2(pk2(rsum[half * 4 + ii]), a[ii], accL);
        u64 tot = fadd2(fadd2(fadd2(accA0, accA1), fadd2(accA2, accA3)), accL);
        if (half == 1) cmb[kp] = tot;
        __syncthreads();
        if (half == 0) {
            float2 t0 = unpk(tot), t1 = unpk(cmb[kp]);
            g_part[pb * 256 + k2]     = 0.5f * (t0.x + t1.x);
            g_part[pb * 256 + k2 + 1] = 0.5f * (t0.y + t1.y);
        }
    }
}

// ---------------- phase Z (97 blocks; block 96 = h2+zH2) ----------------
__global__ __launch_bounds__(256, 4) void phaseZ_k(const float* __restrict__ W2,
                                                   const float* __restrict__ ce_w2,
                                                   const float* __restrict__ ce_b2)
{
    extern __shared__ float smx[];
    int b = blockIdx.x, tid = threadIdx.x;
    auto ldB = [&](int n, int k4) {
        float4 r;
        const float* row = W2 + n * 385;
        r.x = (k4     < 385) ? row[k4]     : 0.f;
        r.y = (k4 + 1 < 385) ? row[k4 + 1] : 0.f;
        r.z = (k4 + 2 < 385) ? row[k4 + 2] : 0.f;
        r.w = (k4 + 3 < 385) ? row[k4 + 3] : 0.f;
        return r;
    };
    if (b < 64) {
        int c = b >> 5, t = b & 31;
        auto ldA = [&](int i, int k4) {
            int g = i * 256 + k4;
            float4 s0 = *(const float4*)&g_H1s[0][g];
            float4 s1 = *(const float4*)&g_H1s[1][g];
            float4 s2q = *(const float4*)&g_H1s[2][g];
            float4 s3 = *(const float4*)&g_H1s[3][g];
            return make_float4(s0.x + s1.x + s2q.x + s3.x, s0.y + s1.y + s2q.y + s3.y,
                               s0.z + s1.z + s2q.z + s3.z, s0.w + s1.w + s2q.w + s3.w);
        };
        gemmDB<false>(smx, ldA, ldB, c * 128, c * 128 + 128,
                      (t >> 2) * 64, (t & 3) * 64, g_Zs[c], 256);
    } else if (b < 96) {
        // c2: K range [320, 385) -- H3 + H4 column (H2v handled via zH2 in opln)
        int t = b - 64;
        auto ldA = [&](int i, int k4) -> float4 {
            if (k4 < 384) return *(const float4*)&g_H3[i * 64 + (k4 - 320)];
            if (k4 == 384) return make_float4((i < 64) ? g_H4v[i] : 0.f, 0.f, 0.f, 0.f);
            return make_float4(0.f, 0.f, 0.f, 0.f);
        };
        gemmDB<false>(smx, ldA, ldB, 320, 385,
                      (t >> 2) * 64, (t & 3) * 64, g_Zs[2], 256);
    } else {
        // h2: gv colsum -> H2v -> zH2
        float* gv = smx;
        float* red = smx + 256;
        float* h2v = smx + 512;
        float acc = 0.f;
#pragma unroll 8
        for (int r = 0; r < 512; r++) acc += g_part[r * 256 + tid];
        gv[tid] = acc;
        __syncthreads();
        int d = tid >> 2, q = tid & 3;
        float p = 0.f;
#pragma unroll 16
        for (int k = q * 64; k < q * 64 + 64; k++) p += ce_w2[d * 256 + k] * gv[k];
        red[tid] = p;
        __syncthreads();
        if (q == 0) h2v[d] = red[tid] + red[tid + 1] + red[tid + 2] + red[tid + 3] + ce_b2[d];
        __syncthreads();
        // zH2[n] = sum_d h2v[d] * W2[n, 256+d]
        float z = 0.f;
        const float* wrow = W2 + tid * 385 + 256;
#pragma unroll 8
        for (int dd = 0; dd < 64; dd++) z = fmaf(h2v[dd], wrow[dd], z);
        g_zH2[tid] = z;
    }
}

// ---------------- opln (128 blocks) ----------------
__global__ __launch_bounds__(256) void opln_k(const float* __restrict__ op_w,
                                              const float* __restrict__ op_b,
                                              const float* __restrict__ ln_g,
                                              const float* __restrict__ ln_b,
                                              float* __restrict__ out)
{
    __shared__ __align__(16) float sA[16][4];
    __shared__ float sB[16][256];
    __shared__ __align__(16) float4 red[256];
    int tid = threadIdx.x;
    int m0 = blockIdx.x * 4;
    float acc[4] = {};
    for (int kc = 0; kc < 256; kc += 16) {
        if (tid < 64) {
            int r = tid >> 4, k = tid & 15;
            int g = (m0 + r) * 256 + kc + k;
            sA[k][r] = g_Zs[0][g] + g_Zs[1][g] + g_Zs[2][g] + g_zH2[kc + k];
        }
#pragma unroll
        for (int s = 0; s < 16; s++) {
            int idx = tid + s * 256;
            int n = idx >> 4, k = idx & 15;
            sB[k][n] = op_w[n * 256 + kc + k];
        }
        __syncthreads();
#pragma unroll
        for (int kk = 0; kk < 16; kk++) {
            float4 a = *(const float4*)&sA[kk][0];
            float bv = sB[kk][tid];
            acc[0] = fmaf(a.x, bv, acc[0]);
            acc[1] = fmaf(a.y, bv, acc[1]);
            acc[2] = fmaf(a.z, bv, acc[2]);
            acc[3] = fmaf(a.w, bv, acc[3]);
        }
        __syncthreads();
    }
    float bias = op_b[tid];
#pragma unroll
    for (int r = 0; r < 4; r++) acc[r] += bias;
    red[tid] = make_float4(acc[0], acc[1], acc[2], acc[3]);
    __syncthreads();
    for (int o = 128; o > 0; o >>= 1) {
        if (tid < o) {
            float4 x = red[tid], y = red[tid + o];
            red[tid] = make_float4(x.x + y.x, x.y + y.y, x.z + y.z, x.w + y.w);
        }
        __syncthreads();
    }
    float4 mu4 = red[0];
    __syncthreads();
    float mu[4] = { mu4.x * (1.f/256.f), mu4.y * (1.f/256.f), mu4.z * (1.f/256.f), mu4.w * (1.f/256.f) };
    float d0 = acc[0] - mu[0], d1 = acc[1] - mu[1], d2 = acc[2] - mu[2], d3 = acc[3] - mu[3];
    red[tid] = make_float4(d0 * d0, d1 * d1, d2 * d2, d3 * d3);
    __syncthreads();
    for (int o = 128; o > 0; o >>= 1) {
        if (tid < o) {
            float4 x = red[tid], y = red[tid + o];
            red[tid] = make_float4(x.x + y.x, x.y + y.y, x.z + y.z, x.w + y.w);
        }
        __syncthreads();
    }
    float4 v4 = red[0];
    float inv[4] = { rsqrtf(v4.x * (1.f/256.f) + 1e-5f), rsqrtf(v4.y * (1.f/256.f) + 1e-5f),
                     rsqrtf(v4.z * (1.f/256.f) + 1e-5f), rsqrtf(v4.w * (1.f/256.f) + 1e-5f) };
    float g = ln_g[tid], bb = ln_b[tid];
    float dd[4] = { d0, d1, d2, d3 };
#pragma unroll
    for (int r = 0; r < 4; r++) {
        float y = dd[r] * inv[r] * g + bb;
        out[(m0 + r) * 256 + tid] = (y > 0.f) ? y : expm1f(y);
    }
}

// ---------------- host ----------------
extern "C" void kernel_launch(void* const* d_in, const int* in_sizes, int n_in,
                              void* d_out, int out_size)
{
    const float* V       = (const float*)d_in[0];
    const int*   adj     = (const int*)d_in[1];
    const float* prev    = (const float*)d_in[2];
    const float* W1      = (const float*)d_in[3];
    const float* sa0     = (const float*)d_in[4];
    const float* sa1     = (const float*)d_in[5];
    const float* ce_w1   = (const float*)d_in[6];
    const float* ce_b1   = (const float*)d_in[7];
    const float* ce_w2   = (const float*)d_in[8];
    const float* ce_b2   = (const float*)d_in[9];
    const float* ca0     = (const float*)d_in[10];
    const float* ca1     = (const float*)d_in[11];
    const float* te_w1   = (const float*)d_in[12];
    const float* te_b1   = (const float*)d_in[13];
    const float* te_w2   = (const float*)d_in[14];
    const float* te_b2   = (const float*)d_in[15];
    const float* pe_w1   = (const float*)d_in[18];
    const float* pe_b1   = (const float*)d_in[19];
    const float* pe_w2   = (const float*)d_in[20];
    const float* pe_b2   = (const float*)d_in[21];
    const float* W2      = (const float*)d_in[24];
    const float* op_w    = (const float*)d_in[25];
    const float* op_b    = (const float*)d_in[26];
    const float* ln_g    = (const float*)d_in[27];
    const float* ln_b    = (const float*)d_in[28];
    float* out = (float*)d_out;

    const int DBSM = 2 * 2 * 16 * 68 * 4;   // 17408 B

    prep_k   <<<65,  256>>>(adj, ce_w2, ca0, ca1);
    phaseA_k <<<512, 256, DBSM>>>(V, prev, W1, ce_w1, te_w1, pe_w1);
    phase2a_k<<<272, 256, DBSM>>>(sa0, sa1, ce_b1, te_w2, te_b1, pe_w2, pe_b1);
    phase2b_k<<<515, 256>>>(adj, te_b2, pe_b2);
    phase2c_k<<<640, 256, DBSM>>>();
    phaseZ_k <<<97,  256, DBSM>>>(W2, ce_w2, ce_b2);
    opln_k   <<<128, 256>>>(op_w, op_b, ln_g, ln_b, out);
}